// round 1
// baseline (speedup 1.0000x reference)
#include <cuda_runtime.h>

// GCN FeatureDiscriminator: B=256, V=512, F=256, O=2
// out[b] = sigmoid( sum_{v,o} relu( (D^-1/2 (A+I) D^-1/2 X W)[v,o] + cb[o] ) * lw[2v+o] + lb )
//
// One CTA per batch. Strategy:
//  - bit-pack (A+I) row masks into smem via ballots (32 KB), degrees via popc
//  - sxw[v,o] = dinv[v] * (X[v,:] @ W[:,o])  (features read once, coalesced float4)
//  - per-row contraction uses register-resident sxw values + broadcast mask reads
// HBM-bound: 384 MB read once -> ~55us floor.

#define BV 512   // vertices
#define BF 256   // features
#define NWARP 16
#define NTHREADS 512
#define ROWS_PER_WARP (BV / NWARP)  // 32

__global__ __launch_bounds__(NTHREADS, 2)
void gcn_disc_kernel(const float* __restrict__ features,
                     const int*   __restrict__ graphs,
                     const float* __restrict__ conv_weight,   // [F,2] row-major
                     const float* __restrict__ conv_bias,     // [2]
                     const float* __restrict__ lin_weight,    // [1, 1024] = [2v+o]
                     const float* __restrict__ lin_bias,      // [1]
                     float* __restrict__ out)                 // [B]
{
    __shared__ unsigned bits[BV][16];   // 512-bit adjacency mask per row (interleaved layout)
    __shared__ float dinv[BV];
    __shared__ float sxw0[BV];          // dinv[w] * (XW)[w,0]
    __shared__ float sxw1[BV];          // dinv[w] * (XW)[w,1]
    __shared__ float lw_s[BV * 2];
    __shared__ float wpart[NWARP];

    const int b    = blockIdx.x;
    const int tid  = threadIdx.x;
    const int wid  = tid >> 5;
    const int lane = tid & 31;

    // stage lin_weight into smem (coalesced)
    for (int i = tid; i < BV * 2; i += NTHREADS) lw_s[i] = lin_weight[i];

    // ---------------- Phase 1: adjacency bitmask + degree --------------------
    // Mask convention (MUST match phase 3 consumption):
    //   bits[v][4c+k] bit 'l'  <->  column w = 128*c + 4*l + k
    const int* gbase = graphs + (size_t)b * BV * BV;
    #pragma unroll 2
    for (int r = 0; r < ROWS_PER_WARP; r++) {
        const int v = wid * ROWS_PER_WARP + r;
        const int4* row = (const int4*)(gbase + (size_t)v * BV);
        int deg = 0;
        #pragma unroll
        for (int c = 0; c < 4; c++) {
            int4 x = row[c * 32 + lane];               // 512B coalesced per warp
            int w0 = c * 128 + 4 * lane;
            unsigned m0 = __ballot_sync(0xffffffffu, (x.x != 0) || (w0     == v));
            unsigned m1 = __ballot_sync(0xffffffffu, (x.y != 0) || (w0 + 1 == v));
            unsigned m2 = __ballot_sync(0xffffffffu, (x.z != 0) || (w0 + 2 == v));
            unsigned m3 = __ballot_sync(0xffffffffu, (x.w != 0) || (w0 + 3 == v));
            if (lane == 0) {
                bits[v][4 * c + 0] = m0;
                bits[v][4 * c + 1] = m1;
                bits[v][4 * c + 2] = m2;
                bits[v][4 * c + 3] = m3;
            }
            deg += __popc(m0) + __popc(m1) + __popc(m2) + __popc(m3);
        }
        if (lane == 0) dinv[v] = rsqrtf((float)deg);   // deg >= 1 (self-loop)
    }

    // ---------------- Phase 2: sxw[v] = dinv[v] * (X[v,:] @ W) ---------------
    // Per-lane fixed W slice: features f = 8*lane .. 8*lane+7
    float w0r[8], w1r[8];
    {
        const float2* cw2 = (const float2*)conv_weight;  // W[f][0],W[f][1] adjacent
        #pragma unroll
        for (int j = 0; j < 8; j++) {
            float2 w = cw2[8 * lane + j];
            w0r[j] = w.x; w1r[j] = w.y;
        }
    }
    const float* fbase = features + (size_t)b * BV * BF;
    #pragma unroll 2
    for (int r = 0; r < ROWS_PER_WARP; r++) {
        const int v = wid * ROWS_PER_WARP + r;
        const float4* frow = (const float4*)(fbase + (size_t)v * BF);
        float4 a  = frow[2 * lane];
        float4 bb = frow[2 * lane + 1];
        float acc0 = a.x * w0r[0];  float acc1 = a.x * w1r[0];
        acc0 = fmaf(a.y,  w0r[1], acc0);  acc1 = fmaf(a.y,  w1r[1], acc1);
        acc0 = fmaf(a.z,  w0r[2], acc0);  acc1 = fmaf(a.z,  w1r[2], acc1);
        acc0 = fmaf(a.w,  w0r[3], acc0);  acc1 = fmaf(a.w,  w1r[3], acc1);
        acc0 = fmaf(bb.x, w0r[4], acc0);  acc1 = fmaf(bb.x, w1r[4], acc1);
        acc0 = fmaf(bb.y, w0r[5], acc0);  acc1 = fmaf(bb.y, w1r[5], acc1);
        acc0 = fmaf(bb.z, w0r[6], acc0);  acc1 = fmaf(bb.z, w1r[6], acc1);
        acc0 = fmaf(bb.w, w0r[7], acc0);  acc1 = fmaf(bb.w, w1r[7], acc1);
        #pragma unroll
        for (int s = 16; s; s >>= 1) {
            acc0 += __shfl_xor_sync(0xffffffffu, acc0, s);
            acc1 += __shfl_xor_sync(0xffffffffu, acc1, s);
        }
        if (lane == 0) {
            float d = dinv[v];           // same warp wrote it in phase 1
            sxw0[v] = d * acc0;
            sxw1[v] = d * acc1;
        }
    }
    __syncthreads();  // bits[] and sxw[] now globally visible

    // ---------------- Phase 3: y[v] = dinv[v] * (mask . sxw), head dot -------
    // Preload this lane's fixed 16 sxw pairs: w = 128*c + 4*lane + k
    float r0[16], r1[16];
    #pragma unroll
    for (int c = 0; c < 4; c++) {
        #pragma unroll
        for (int k = 0; k < 4; k++) {
            int w = 128 * c + 4 * lane + k;
            r0[4 * c + k] = sxw0[w];
            r1[4 * c + k] = sxw1[w];
        }
    }
    const float cb0 = conv_bias[0];
    const float cb1 = conv_bias[1];

    float part = 0.0f;
    for (int r = 0; r < ROWS_PER_WARP; r++) {
        const int v = wid * ROWS_PER_WARP + r;
        float acc0 = 0.0f, acc1 = 0.0f;
        #pragma unroll
        for (int c = 0; c < 4; c++) {
            #pragma unroll
            for (int k = 0; k < 4; k++) {
                unsigned m = bits[v][4 * c + k];      // broadcast LDS
                if ((m >> lane) & 1u) {
                    acc0 += r0[4 * c + k];
                    acc1 += r1[4 * c + k];
                }
            }
        }
        #pragma unroll
        for (int s = 16; s; s >>= 1) {
            acc0 += __shfl_xor_sync(0xffffffffu, acc0, s);
            acc1 += __shfl_xor_sync(0xffffffffu, acc1, s);
        }
        if (lane == 0) {
            float d  = dinv[v];
            float h0 = fmaxf(fmaf(d, acc0, cb0), 0.0f);
            float h1 = fmaxf(fmaf(d, acc1, cb1), 0.0f);
            part = fmaf(h0, lw_s[2 * v], part);
            part = fmaf(h1, lw_s[2 * v + 1], part);
        }
    }
    if (lane == 0) wpart[wid] = part;
    __syncthreads();

    // ---------------- Final reduce + sigmoid ---------------------------------
    if (wid == 0) {
        float s = (lane < NWARP) ? wpart[lane] : 0.0f;
        #pragma unroll
        for (int sh = 8; sh; sh >>= 1) s += __shfl_xor_sync(0xffffffffu, s, sh);
        if (lane == 0) {
            float logit = s + lin_bias[0];
            out[b] = 1.0f / (1.0f + expf(-logit));
        }
    }
}

extern "C" void kernel_launch(void* const* d_in, const int* in_sizes, int n_in,
                              void* d_out, int out_size) {
    const float* features    = (const float*)d_in[0];
    const int*   graphs      = (const int*)  d_in[1];
    const float* conv_weight = (const float*)d_in[2];
    const float* conv_bias   = (const float*)d_in[3];
    const float* lin_weight  = (const float*)d_in[4];
    const float* lin_bias    = (const float*)d_in[5];
    float* out = (float*)d_out;

    gcn_disc_kernel<<<256, NTHREADS>>>(features, graphs, conv_weight, conv_bias,
                                       lin_weight, lin_bias, out);
}

// round 2
// speedup vs baseline: 1.0537x; 1.0537x over previous
#include <cuda_runtime.h>

// GCN FeatureDiscriminator: B=256, V=512, F=256, O=2
// Two-kernel split:
//   A: perfectly-balanced row-local streaming pass over graphs (256MB) +
//      features (128MB) -> bits (8MB), dinv (0.5MB), xw (1MB) scratch.
//   B: per-batch aggregation y = D^-1/2 (A+I) D^-1/2 X W, relu, head dot, sigmoid.

#define BATCH 256
#define BV 512
#define BF 256
#define NROWS (BATCH * BV)        // 131072
#define NTHREADS 512
#define NWARP 16
#define GRID_A 304                // ~2 CTAs/SM on 152-SM GB300
#define TOTAL_WARPS_A (GRID_A * NWARP)

// scratch (allocation-free: __device__ globals)
__device__ unsigned g_bits[NROWS * 16];   // 8 MB: 512-bit mask per row
__device__ float    g_dinv[NROWS];        // 0.5 MB
__device__ float2   g_xw[NROWS];          // 1 MB: X[v,:] @ W (unscaled)

// ---------------------------------------------------------------------------
// Kernel A: row-local streaming. Warp per row, grid-stride.
// Bit convention: bits[row][4c+k] bit 'l'  <->  column w = 128*c + 4*l + k
// ---------------------------------------------------------------------------
__global__ __launch_bounds__(NTHREADS, 2)
void gcn_rows_kernel(const float* __restrict__ features,
                     const int*   __restrict__ graphs,
                     const float* __restrict__ conv_weight)   // [F,2] row-major
{
    const int tid  = threadIdx.x;
    const int wid  = tid >> 5;
    const int lane = tid & 31;
    const int gwarp = blockIdx.x * NWARP + wid;

    // per-lane fixed W slice: features f = 8*lane .. 8*lane+7
    float w0r[8], w1r[8];
    {
        const float2* cw2 = (const float2*)conv_weight;
        #pragma unroll
        for (int j = 0; j < 8; j++) {
            float2 w = __ldg(cw2 + 8 * lane + j);
            w0r[j] = w.x; w1r[j] = w.y;
        }
    }

    for (int row = gwarp; row < NROWS; row += TOTAL_WARPS_A) {
        const int v = row & (BV - 1);
        const int4*   grow = (const int4*)graphs + (size_t)row * (BV / 4);
        const float4* frow = (const float4*)features + (size_t)row * (BF / 4);

        // issue all 6 streaming loads up front (MLP)
        int4 x0 = __ldcs(grow + 0 * 32 + lane);
        int4 x1 = __ldcs(grow + 1 * 32 + lane);
        int4 x2 = __ldcs(grow + 2 * 32 + lane);
        int4 x3 = __ldcs(grow + 3 * 32 + lane);
        float4 fa = __ldcs(frow + 2 * lane);
        float4 fb = __ldcs(frow + 2 * lane + 1);

        // adjacency bitmask + degree (ballot results are warp-uniform)
        int deg = 0;
        #pragma unroll
        for (int c = 0; c < 4; c++) {
            int4 x = (c == 0) ? x0 : (c == 1) ? x1 : (c == 2) ? x2 : x3;
            int w0 = 128 * c + 4 * lane;
            unsigned m0 = __ballot_sync(0xffffffffu, (x.x != 0) || (w0     == v));
            unsigned m1 = __ballot_sync(0xffffffffu, (x.y != 0) || (w0 + 1 == v));
            unsigned m2 = __ballot_sync(0xffffffffu, (x.z != 0) || (w0 + 2 == v));
            unsigned m3 = __ballot_sync(0xffffffffu, (x.w != 0) || (w0 + 3 == v));
            deg += __popc(m0) + __popc(m1) + __popc(m2) + __popc(m3);
            if (lane == c) {
                ((uint4*)g_bits)[(size_t)row * 4 + c] = make_uint4(m0, m1, m2, m3);
            }
        }
        if (lane == 4) g_dinv[row] = rsqrtf((float)deg);   // deg >= 1 (self-loop)

        // xw = X[row,:] @ W  (warp butterfly reduce)
        float acc0 = fa.x * w0r[0];             float acc1 = fa.x * w1r[0];
        acc0 = fmaf(fa.y, w0r[1], acc0);        acc1 = fmaf(fa.y, w1r[1], acc1);
        acc0 = fmaf(fa.z, w0r[2], acc0);        acc1 = fmaf(fa.z, w1r[2], acc1);
        acc0 = fmaf(fa.w, w0r[3], acc0);        acc1 = fmaf(fa.w, w1r[3], acc1);
        acc0 = fmaf(fb.x, w0r[4], acc0);        acc1 = fmaf(fb.x, w1r[4], acc1);
        acc0 = fmaf(fb.y, w0r[5], acc0);        acc1 = fmaf(fb.y, w1r[5], acc1);
        acc0 = fmaf(fb.z, w0r[6], acc0);        acc1 = fmaf(fb.z, w1r[6], acc1);
        acc0 = fmaf(fb.w, w0r[7], acc0);        acc1 = fmaf(fb.w, w1r[7], acc1);
        #pragma unroll
        for (int s = 16; s; s >>= 1) {
            acc0 += __shfl_xor_sync(0xffffffffu, acc0, s);
            acc1 += __shfl_xor_sync(0xffffffffu, acc1, s);
        }
        if (lane == 5) g_xw[row] = make_float2(acc0, acc1);
    }
}

// ---------------------------------------------------------------------------
// Kernel B: per-batch aggregation + head. One CTA per batch.
// ---------------------------------------------------------------------------
__global__ __launch_bounds__(NTHREADS, 2)
void gcn_agg_kernel(const float* __restrict__ conv_bias,
                    const float* __restrict__ lin_weight,   // [1, 1024] = [2v+o]
                    const float* __restrict__ lin_bias,
                    float* __restrict__ out)
{
    __shared__ unsigned bits[BV][16];
    __shared__ float s0[BV];            // dinv[w] * xw[w].x
    __shared__ float s1[BV];            // dinv[w] * xw[w].y
    __shared__ float dinv_s[BV];
    __shared__ float lw_s[BV * 2];
    __shared__ float wpart[NWARP];

    const int b    = blockIdx.x;
    const int tid  = threadIdx.x;
    const int wid  = tid >> 5;
    const int lane = tid & 31;

    // stage scratch -> smem (all coalesced)
    {
        const uint4* src = (const uint4*)g_bits + (size_t)b * (BV * 4);
        uint4* dst = (uint4*)bits;
        #pragma unroll
        for (int i = 0; i < 4; i++) dst[tid + i * NTHREADS] = src[tid + i * NTHREADS];

        float d = g_dinv[b * BV + tid];
        float2 xw = g_xw[b * BV + tid];
        dinv_s[tid] = d;
        s0[tid] = d * xw.x;
        s1[tid] = d * xw.y;

        lw_s[tid]            = lin_weight[tid];
        lw_s[tid + NTHREADS] = lin_weight[tid + NTHREADS];
    }
    __syncthreads();

    // preload this lane's fixed 16 sxw pairs: w = 128*c + 4*lane + k
    float r0[16], r1[16];
    #pragma unroll
    for (int c = 0; c < 4; c++) {
        #pragma unroll
        for (int k = 0; k < 4; k++) {
            int w = 128 * c + 4 * lane + k;
            r0[4 * c + k] = s0[w];
            r1[4 * c + k] = s1[w];
        }
    }
    const float cb0 = conv_bias[0];
    const float cb1 = conv_bias[1];

    float part = 0.0f;
    #pragma unroll 2
    for (int r = 0; r < BV / NWARP; r++) {
        const int v = wid * (BV / NWARP) + r;
        float acc0 = 0.0f, acc1 = 0.0f;
        #pragma unroll
        for (int j = 0; j < 16; j++) {
            unsigned m = bits[v][j];            // broadcast LDS
            if ((m >> lane) & 1u) {
                acc0 += r0[j];
                acc1 += r1[j];
            }
        }
        #pragma unroll
        for (int s = 16; s; s >>= 1) {
            acc0 += __shfl_xor_sync(0xffffffffu, acc0, s);
            acc1 += __shfl_xor_sync(0xffffffffu, acc1, s);
        }
        if (lane == 0) {
            float d  = dinv_s[v];
            float h0 = fmaxf(fmaf(d, acc0, cb0), 0.0f);
            float h1 = fmaxf(fmaf(d, acc1, cb1), 0.0f);
            part = fmaf(h0, lw_s[2 * v], part);
            part = fmaf(h1, lw_s[2 * v + 1], part);
        }
    }
    if (lane == 0) wpart[wid] = part;
    __syncthreads();

    if (wid == 0) {
        float s = (lane < NWARP) ? wpart[lane] : 0.0f;
        #pragma unroll
        for (int sh = 8; sh; sh >>= 1) s += __shfl_xor_sync(0xffffffffu, s, sh);
        if (lane == 0) {
            float logit = s + lin_bias[0];
            out[b] = 1.0f / (1.0f + expf(-logit));
        }
    }
}

extern "C" void kernel_launch(void* const* d_in, const int* in_sizes, int n_in,
                              void* d_out, int out_size) {
    const float* features    = (const float*)d_in[0];
    const int*   graphs      = (const int*)  d_in[1];
    const float* conv_weight = (const float*)d_in[2];
    const float* conv_bias   = (const float*)d_in[3];
    const float* lin_weight  = (const float*)d_in[4];
    const float* lin_bias    = (const float*)d_in[5];
    float* out = (float*)d_out;

    gcn_rows_kernel<<<GRID_A, NTHREADS>>>(features, graphs, conv_weight);
    gcn_agg_kernel<<<BATCH, NTHREADS>>>(conv_bias, lin_weight, lin_bias, out);
}